// round 5
// baseline (speedup 1.0000x reference)
#include <cuda_runtime.h>

#define BB   32
#define NN   1024
#define WW_  128
#define RR   4
#define SEQ  512
#define DIN  512
#define IFACE 919

// Flattened output offsets (tuple concat order: out, memory, link, usage, prec, ww, rw)
#define OUT_OFF    0ull
#define MEM_OFF    16384ull
#define LINK_OFF   4210688ull
#define USAGE_OFF  37765120ull
#define PREC_OFF   37797888ull
#define WWO_OFF    37830656ull
#define RW_OFF     37863424ull
#define LINK_F4    8388608ull      // 33,554,432 floats / 4

#define MEAN_BLKS  512
#define ZERO_BLKS  1856
#define N1_BLKS    (MEAN_BLKS + ZERO_BLKS)

// Scratch (no allocations allowed)
__device__ float g_part[32 * BB * DIN];   // 32 chunk-halves per batch
__device__ float g_er[BB * WW_];
__device__ float g_wv[BB * WW_];
__device__ float g_q[BB * RR];
__device__ float g_u[BB];

__device__ __forceinline__ float sigmoidf(float x) {
    return 1.0f / (1.0f + expf(-x));
}

// ---------------------------------------------------------------------------
// Node 1: fused link-zero (134MB, plain stores -> stays in L2 across replays)
//         + mean partials of x (33.5MB, __ldcs evict-first streaming reads).
// grid 2368 x 256. No inter-block deps, no sync, no spin.
// ---------------------------------------------------------------------------
__global__ void __launch_bounds__(256)
k1_zero_mean(const float* __restrict__ x, float* __restrict__ out) {
    int bid = blockIdx.x, t = threadIdx.x;
    if (bid < MEAN_BLKS) {
        // block (b, c): 32-row chunk c of batch b; threads split into 2 halves
        int b = bid >> 4, c = bid & 15;
        int col = t & 127;          // float4 column (512 floats / 4)
        int h   = t >> 7;           // 16-row half
        int cc  = c * 2 + h;        // chunk-half id in [0, 32)
        const float4* xp = (const float4*)(x + (size_t)b * SEQ * DIN);
        float4 acc = make_float4(0.f, 0.f, 0.f, 0.f);
        int s0 = c * 32 + h * 16;
#pragma unroll
        for (int s = s0; s < s0 + 16; s++) {
            float4 v = __ldcs(&xp[s * 128 + col]);   // read-once: evict-first
            acc.x += v.x; acc.y += v.y; acc.z += v.z; acc.w += v.w;
        }
        ((float4*)g_part)[(cc * BB + b) * 128 + col] = acc;
    } else {
        float4 z = make_float4(0.f, 0.f, 0.f, 0.f);
        float4* p = (float4*)(out + LINK_OFF);
        size_t stride = (size_t)ZERO_BLKS * 256;
        for (size_t i = (size_t)(bid - MEAN_BLKS) * 256 + t; i < LINK_F4; i += stride)
            p[i] = z;
    }
}

// ---------------------------------------------------------------------------
// Node 2: one block per batch. Combine 32 partial chunks -> mean (smem),
// compute only the needed iface columns [645,919), activations, out/ww/prec.
// ---------------------------------------------------------------------------
__global__ void __launch_bounds__(256)
k2_batch(const float* __restrict__ Wm, float* __restrict__ out) {
    int b = blockIdx.x, t = threadIdx.x;
    __shared__ float mx[DIN];
    __shared__ float s_rm1[RR], s_fg[RR], s_q[RR];
    __shared__ float s_pw[16];
    __shared__ float s_c1, s_c2;

    for (int i = t; i < DIN; i += 256) {
        float s = 0.f;
#pragma unroll
        for (int c = 0; c < 32; c++) s += g_part[(c * BB + b) * DIN + i];
        mx[i] = s * (1.0f / 512.0f);
    }
    __syncthreads();

    // iface[j] = mean . W[:,j] for j in [645, 919)
    float f_loc[2];
    int   j_loc[2];
    int nj = 0;
    for (int j = 645 + t; j < IFACE; j += 256) {
        float acc = 0.f;
#pragma unroll 8
        for (int k = 0; k < DIN; k++) acc = fmaf(mx[k], Wm[k * IFACE + j], acc);
        f_loc[nj] = acc; j_loc[nj] = j; nj++;
    }
    __syncthreads();
    // scatter: mx[0..127]=erase raw, [128..255]=write_vec, [256..259]=free gates,
    // [260]=alloc gate, [261]=write gate, [262..273]=read modes
    for (int i = 0; i < nj; i++) mx[j_loc[i] - 645] = f_loc[i];
    __syncthreads();

    if (t < 128) {
        g_er[b * WW_ + t] = sigmoidf(mx[t]);
        g_wv[b * WW_ + t] = mx[128 + t];
    }
    if (t < RR) {
        float m0 = mx[262 + t], m1 = mx[266 + t], m2 = mx[270 + t];
        float mmax = fmaxf(m0, fmaxf(m1, m2));
        float e0 = expf(m0 - mmax), e1 = expf(m1 - mmax), e2 = expf(m2 - mmax);
        float rm1 = e1 / (e0 + e1 + e2);
        s_rm1[t] = rm1;
        float q = rm1 * (1.0f / 1024.0f);   // exact /2^10
        s_q[t] = q;
        g_q[b * RR + t] = q;
        s_fg[t] = sigmoidf(mx[256 + t]);
    }
    __syncthreads();
    if (t == 0) {
        float ret = 1.0f;
#pragma unroll
        for (int r = 0; r < RR; r++) ret *= (1.0f - s_fg[r] * s_q[r]);
        float u = 1e-6f * ret;              // usage (constant over n)
        g_u[b] = u;
        float ag = sigmoidf(mx[260]);
        float wg = sigmoidf(mx[261]);
        s_c1 = wg * ag * (1.0f - u);
        s_c2 = wg * (1.0f - ag) * (1.0f / 1024.0f);
        float sh = 1.0f;                    // exact sequential cumprod prefix
#pragma unroll
        for (int i = 0; i < 16; i++) { s_pw[i] = sh; sh *= u; }
    }
    __syncthreads();

    // out[b, w*4+r] = 1e-6 * rm1[r]
    if (t < 128) {
        float4 ov = make_float4(1e-6f * s_rm1[0], 1e-6f * s_rm1[1],
                                1e-6f * s_rm1[2], 1e-6f * s_rm1[3]);
        ((float4*)(out + OUT_OFF))[b * 128 + t] = ov;
    }
    // ww / prec sections
    float c1 = s_c1, c2 = s_c2;
#pragma unroll
    for (int n = t; n < NN; n += 256) {
        float shifted = (n < 16) ? s_pw[n] : 0.0f;
        float ww = fmaf(c1, shifted, c2);
        out[WWO_OFF + (size_t)b * NN + n]  = ww;
        out[PREC_OFF + (size_t)b * NN + n] = ww;  // prec == ww
    }
}

// ---------------------------------------------------------------------------
// Node 3: fills. grid 1088, block 256.
//   bid 0..1023   : memory (16.8MB), 4 float4 per thread
//   bid 1024..1055: rw, 4 float4 per thread
//   bid 1056..1087: usage, 4 floats per thread
// ---------------------------------------------------------------------------
__global__ void __launch_bounds__(256)
k3_fill(float* __restrict__ out) {
    int bid = blockIdx.x, t = threadIdx.x;
    if (bid < 1024) {
        int v0 = bid * 1024;
#pragma unroll
        for (int i = 0; i < 4; i++) {
            int v = v0 + i * 256 + t;       // float4 index into memory
            int b = v >> 15;                // 32768 f4 per batch
            int rem = v & 32767;
            int n  = rem >> 5;
            int w4 = rem & 31;
            float ww = __ldg(out + WWO_OFF + (size_t)b * NN + n);
            float4 e  = ((const float4*)g_er)[b * 32 + w4];
            float4 wv = ((const float4*)g_wv)[b * 32 + w4];
            float4 m;
            m.x = 1e-6f * (1.0f - ww * e.x) + ww * wv.x;
            m.y = 1e-6f * (1.0f - ww * e.y) + ww * wv.y;
            m.z = 1e-6f * (1.0f - ww * e.z) + ww * wv.z;
            m.w = 1e-6f * (1.0f - ww * e.w) + ww * wv.w;
            ((float4*)(out + MEM_OFF))[v] = m;
        }
    } else if (bid < 1056) {
        int base = (bid - 1024) * 1024;
#pragma unroll
        for (int i = 0; i < 4; i++) {
            int v = base + i * 256 + t;     // (b,n) index, f4 over r
            ((float4*)(out + RW_OFF))[v] = ((const float4*)g_q)[v >> 10];
        }
    } else {
        int base = (bid - 1056) * 1024;
#pragma unroll
        for (int i = 0; i < 4; i++) {
            int v = base + i * 256 + t;
            out[USAGE_OFF + v] = g_u[v >> 10];
        }
    }
}

extern "C" void kernel_launch(void* const* d_in, const int* in_sizes, int n_in,
                              void* d_out, int out_size) {
    const float* x  = (const float*)d_in[0];
    const float* Wm = (const float*)d_in[1];
    float* out = (float*)d_out;

    k1_zero_mean<<<N1_BLKS, 256>>>(x, out);
    k2_batch<<<BB, 256>>>(Wm, out);
    k3_fill<<<1088, 256>>>(out);
}